// round 2
// baseline (speedup 1.0000x reference)
#include <cuda_runtime.h>

// Collapse the purely-linear 4-GEMM chain:
//   out = x @ (w1 @ w2 @ w3 @ w4)     per expert
// Stage 1: W12 = w1@w2   [E,1024,1024]  (K=512)
// Stage 2: W34 = w3@w4   [E,1024,1024]  (K=512)
// Stage 3: W   = W12@W34 [E,1024,1024]  (K=1024)
// Stage 4: out = x@W     [E,4096,1024]  (K=1024)

#define BM 128
#define BN 128
#define BK 16

__device__ float g_w12[8u * 1024u * 1024u];
__device__ float g_w34[8u * 1024u * 1024u];
__device__ float g_wc [8u * 1024u * 1024u];

__global__ __launch_bounds__(256, 2)
void sgemm_batched(const float* __restrict__ A,   // [E, M, K] row-major
                   const float* __restrict__ B,   // [E, K, N] row-major
                   float* __restrict__ C,         // [E, M, N] row-major
                   int M, int N, int K)
{
    __shared__ float As[BK][BM];   // transposed A tile: As[k][m]
    __shared__ float Bs[BK][BN];

    const int e = blockIdx.z;
    const float* Ae = A + (size_t)e * M * K;
    const float* Be = B + (size_t)e * K * N;
    float*       Ce = C + (size_t)e * M * N;

    const int bm = blockIdx.y * BM;
    const int bn = blockIdx.x * BN;

    const int tid = threadIdx.x;
    const int tx  = tid & 15;   // 0..15 -> 8 output cols each
    const int ty  = tid >> 4;   // 0..15 -> 8 output rows each

    // A tile: 128 rows x 16 floats = 512 float4; 2 per thread.
    const int ar0 = tid >> 2,          aq0 = tid & 3;
    const int ar1 = (tid + 256) >> 2,  aq1 = (tid + 256) & 3;
    // B tile: 16 rows x 128 floats = 512 float4; 2 per thread.
    const int bk0 = tid >> 5,          bq0 = tid & 31;
    const int bk1 = (tid + 256) >> 5,  bq1 = (tid + 256) & 31;

    // Prefetch tile k0=0 into registers (global latency overlaps nothing yet,
    // but subsequent tiles overlap with compute).
    float4 a0 = *(const float4*)&Ae[(size_t)(bm + ar0) * K + aq0 * 4];
    float4 a1 = *(const float4*)&Ae[(size_t)(bm + ar1) * K + aq1 * 4];
    float4 b0 = *(const float4*)&Be[(size_t)bk0 * N + bn + bq0 * 4];
    float4 b1 = *(const float4*)&Be[(size_t)bk1 * N + bn + bq1 * 4];

    float acc[8][8];
    #pragma unroll
    for (int i = 0; i < 8; i++)
        #pragma unroll
        for (int j = 0; j < 8; j++) acc[i][j] = 0.0f;

    for (int k0 = 0; k0 < K; k0 += BK) {
        // Stage registers -> smem (A transposed)
        As[aq0 * 4 + 0][ar0] = a0.x;
        As[aq0 * 4 + 1][ar0] = a0.y;
        As[aq0 * 4 + 2][ar0] = a0.z;
        As[aq0 * 4 + 3][ar0] = a0.w;
        As[aq1 * 4 + 0][ar1] = a1.x;
        As[aq1 * 4 + 1][ar1] = a1.y;
        As[aq1 * 4 + 2][ar1] = a1.z;
        As[aq1 * 4 + 3][ar1] = a1.w;
        *(float4*)&Bs[bk0][bq0 * 4] = b0;
        *(float4*)&Bs[bk1][bq1 * 4] = b1;
        __syncthreads();

        // Prefetch next tile while computing this one
        if (k0 + BK < K) {
            const int kn = k0 + BK;
            a0 = *(const float4*)&Ae[(size_t)(bm + ar0) * K + kn + aq0 * 4];
            a1 = *(const float4*)&Ae[(size_t)(bm + ar1) * K + kn + aq1 * 4];
            b0 = *(const float4*)&Be[(size_t)(kn + bk0) * N + bn + bq0 * 4];
            b1 = *(const float4*)&Be[(size_t)(kn + bk1) * N + bn + bq1 * 4];
        }

        #pragma unroll
        for (int kk = 0; kk < BK; kk++) {
            float4 av0 = *(const float4*)&As[kk][ty * 8];
            float4 av1 = *(const float4*)&As[kk][ty * 8 + 4];
            float4 bv0 = *(const float4*)&Bs[kk][tx * 8];
            float4 bv1 = *(const float4*)&Bs[kk][tx * 8 + 4];
            float a[8] = {av0.x, av0.y, av0.z, av0.w, av1.x, av1.y, av1.z, av1.w};
            float b[8] = {bv0.x, bv0.y, bv0.z, bv0.w, bv1.x, bv1.y, bv1.z, bv1.w};
            #pragma unroll
            for (int i = 0; i < 8; i++)
                #pragma unroll
                for (int j = 0; j < 8; j++)
                    acc[i][j] = fmaf(a[i], b[j], acc[i][j]);
        }
        __syncthreads();
    }

    #pragma unroll
    for (int i = 0; i < 8; i++) {
        float* cp = &Ce[(size_t)(bm + ty * 8 + i) * N + bn + tx * 8];
        *(float4*)(cp)     = make_float4(acc[i][0], acc[i][1], acc[i][2], acc[i][3]);
        *(float4*)(cp + 4) = make_float4(acc[i][4], acc[i][5], acc[i][6], acc[i][7]);
    }
}

extern "C" void kernel_launch(void* const* d_in, const int* in_sizes, int n_in,
                              void* d_out, int out_size)
{
    (void)in_sizes; (void)n_in; (void)out_size;
    const float* x  = (const float*)d_in[0];
    const float* w1 = (const float*)d_in[1];
    const float* w2 = (const float*)d_in[2];
    const float* w3 = (const float*)d_in[3];
    const float* w4 = (const float*)d_in[4];
    float* out = (float*)d_out;

    float *w12, *w34, *wc;
    cudaGetSymbolAddress((void**)&w12, g_w12);
    cudaGetSymbolAddress((void**)&w34, g_w34);
    cudaGetSymbolAddress((void**)&wc,  g_wc);

    const int E = 8, T = 4096, H = 1024, I = 512;
    dim3 blk(256);

    // W12 = w1 @ w2 : [E,H,I]@[E,I,H] -> [E,H,H]
    sgemm_batched<<<dim3(H / BN, H / BM, E), blk>>>(w1, w2, w12, H, H, I);
    // W34 = w3 @ w4
    sgemm_batched<<<dim3(H / BN, H / BM, E), blk>>>(w3, w4, w34, H, H, I);
    // W = W12 @ W34 : K = H
    sgemm_batched<<<dim3(H / BN, H / BM, E), blk>>>(w12, w34, wc, H, H, H);
    // out = x @ W : [E,T,H]@[E,H,H] -> [E,T,H]
    sgemm_batched<<<dim3(H / BN, T / BM, E), blk>>>(x, wc, out, T, H, H);
}

// round 6
// speedup vs baseline: 2.4181x; 2.4181x over previous
#include <cuda_runtime.h>
#include <cuda_bf16.h>
#include <cstdint>

// out = x @ (w1@w2@w3@w4) per expert; every GEMM = bf16 hi/lo split (3 HMMA terms),
// computed as D[M,N] = A[M,K] * Bt[N,K]^T via mma.sync.m16n8k16 (sm_80+ PTX only —
// tcgen05 is rejected because the harness compiles through compute_103 virtual arch).

#define NE 8
#define NT 4096
#define NH 1024
#define NI 512

// ---------------- scratch ----------------
__device__ __align__(128) __nv_bfloat16 g_xh[NE*NT*NH],  g_xl[NE*NT*NH];
__device__ __align__(128) __nv_bfloat16 g_w1h[NE*NH*NI], g_w1l[NE*NH*NI];
__device__ __align__(128) __nv_bfloat16 g_w2h[NE*NH*NI], g_w2l[NE*NH*NI];   // w2^T
__device__ __align__(128) __nv_bfloat16 g_w3h[NE*NH*NI], g_w3l[NE*NH*NI];
__device__ __align__(128) __nv_bfloat16 g_w4h[NE*NH*NI], g_w4l[NE*NH*NI];   // w4^T
__device__ __align__(128) __nv_bfloat16 g_W12h[NE*NH*NH], g_W12l[NE*NH*NH];
__device__ __align__(128) __nv_bfloat16 g_W34h[NE*NH*NH], g_W34l[NE*NH*NH]; // W34^T
__device__ __align__(128) __nv_bfloat16 g_Wth[NE*NH*NH],  g_Wtl[NE*NH*NH];  // W^T

__device__ __forceinline__ void split1(float v, __nv_bfloat16& h, __nv_bfloat16& l) {
    h = __float2bfloat16(v);
    l = __float2bfloat16(v - __bfloat162float(h));
}

// ---------------- conversion kernels ----------------
__global__ __launch_bounds__(256)
void split_rm(const float4* __restrict__ in, uint2* __restrict__ hi,
              uint2* __restrict__ lo, int n4) {
    int i = blockIdx.x * 256 + threadIdx.x;
    if (i >= n4) return;
    float4 v = in[i];
    __nv_bfloat16 h[4], l[4];
    split1(v.x, h[0], l[0]); split1(v.y, h[1], l[1]);
    split1(v.z, h[2], l[2]); split1(v.w, h[3], l[3]);
    hi[i] = *(uint2*)h;
    lo[i] = *(uint2*)l;
}

// in: [E, R, C] fp32 -> out: [E, C, R] bf16 hi/lo
__global__ __launch_bounds__(256)
void split_tr(const float* __restrict__ in, __nv_bfloat16* __restrict__ hi,
              __nv_bfloat16* __restrict__ lo, int R, int C) {
    __shared__ float t[32][33];
    const int e = blockIdx.z;
    const float* ine = in + (size_t)e * R * C;
    __nv_bfloat16* he = hi + (size_t)e * R * C;
    __nv_bfloat16* le = lo + (size_t)e * R * C;
    const int r0 = blockIdx.y * 32, c0 = blockIdx.x * 32;
    const int tx = threadIdx.x & 31, ty = threadIdx.x >> 5;
    #pragma unroll
    for (int i = 0; i < 32; i += 8)
        t[ty + i][tx] = ine[(size_t)(r0 + ty + i) * C + c0 + tx];
    __syncthreads();
    #pragma unroll
    for (int i = 0; i < 32; i += 8) {
        __nv_bfloat16 h, l;
        split1(t[tx][ty + i], h, l);
        he[(size_t)(c0 + ty + i) * R + r0 + tx] = h;
        le[(size_t)(c0 + ty + i) * R + r0 + tx] = l;
    }
}

// ---------------- HMMA bf16x3 GEMM ----------------
// CTA 128x128, BK=32. 8 warps in 4(M) x 2(N); warp tile 32x64.
// SMEM rows padded to 80B (32 bf16 = 64B data + 16B pad) -> ldmatrix conflict-free.
#define BM 128
#define BN 128
#define BKC 32
#define ROWB 80u
#define TILEB (128u * ROWB)      // 10240 B per 128x32 tile
#define BUFB (4u * TILEB)        // Ah | Al | Bh | Bl
#define SMEMB (2u * BUFB)        // 81920 B double-buffered

__device__ __forceinline__ void cp16(uint32_t s, const void* g) {
    asm volatile("cp.async.cg.shared.global [%0], [%1], 16;" :: "r"(s), "l"(g));
}
__device__ __forceinline__ void ldm4(uint32_t* r, uint32_t addr) {
    asm volatile("ldmatrix.sync.aligned.m8n8.x4.shared.b16 {%0,%1,%2,%3}, [%4];"
                 : "=r"(r[0]), "=r"(r[1]), "=r"(r[2]), "=r"(r[3]) : "r"(addr));
}
__device__ __forceinline__ void mma16816(float* c, const uint32_t* a, uint32_t b0, uint32_t b1) {
    asm volatile("mma.sync.aligned.m16n8k16.row.col.f32.bf16.bf16.f32 "
                 "{%0,%1,%2,%3}, {%4,%5,%6,%7}, {%8,%9}, {%0,%1,%2,%3};"
                 : "+f"(c[0]), "+f"(c[1]), "+f"(c[2]), "+f"(c[3])
                 : "r"(a[0]), "r"(a[1]), "r"(a[2]), "r"(a[3]), "r"(b0), "r"(b1));
}

template<bool SPLIT_OUT>
__global__ __launch_bounds__(256, 2)
void gemm_hmma_x3(const __nv_bfloat16* __restrict__ Ah, const __nv_bfloat16* __restrict__ Al,
                  const __nv_bfloat16* __restrict__ Bh, const __nv_bfloat16* __restrict__ Bl,
                  float* __restrict__ Cf,
                  __nv_bfloat16* __restrict__ Ch, __nv_bfloat16* __restrict__ Cl,
                  int M, int N, int K)
{
    extern __shared__ __align__(128) char smem[];
    const uint32_t sb = (uint32_t)__cvta_generic_to_shared(smem);

    const int tid = threadIdx.x;
    const int lane = tid & 31;
    const int wid = tid >> 5;
    const int wm = (wid & 3) * 32;   // warp M offset in CTA tile
    const int wn = (wid >> 2) * 64;  // warp N offset
    const int g = lane >> 3, r8 = lane & 7;

    const int e = blockIdx.z;
    const size_t MK = (size_t)M * K, NK = (size_t)N * K, MN = (size_t)M * N;
    const __nv_bfloat16 *Ahe = Ah + e * MK, *Ale = Al + e * MK;
    const __nv_bfloat16 *Bhe = Bh + e * NK, *Ble = Bl + e * NK;
    const int bm = blockIdx.y * BM, bn = blockIdx.x * BN;

    float acc[2][8][4];
    #pragma unroll
    for (int i = 0; i < 2; i++)
        #pragma unroll
        for (int j = 0; j < 8; j++)
            #pragma unroll
            for (int q = 0; q < 4; q++) acc[i][j][q] = 0.0f;

    const int NC = K / BKC;

    // per-thread copy coords: 2 chunks of 16B per 128x32 tile
    const int cr0 = tid >> 2,          cc0 = tid & 3;
    const int cr1 = (tid + 256) >> 2,  cc1 = (tid + 256) & 3;

    auto load_chunk = [&](int c, int buf) {
        const int k0 = c * BKC;
        const uint32_t b = sb + (uint32_t)buf * BUFB;
        // Ah, Al
        cp16(b + cr0 * ROWB + cc0 * 16, Ahe + (size_t)(bm + cr0) * K + k0 + cc0 * 8);
        cp16(b + cr1 * ROWB + cc1 * 16, Ahe + (size_t)(bm + cr1) * K + k0 + cc1 * 8);
        cp16(b + TILEB + cr0 * ROWB + cc0 * 16, Ale + (size_t)(bm + cr0) * K + k0 + cc0 * 8);
        cp16(b + TILEB + cr1 * ROWB + cc1 * 16, Ale + (size_t)(bm + cr1) * K + k0 + cc1 * 8);
        // Bh, Bl
        cp16(b + 2 * TILEB + cr0 * ROWB + cc0 * 16, Bhe + (size_t)(bn + cr0) * K + k0 + cc0 * 8);
        cp16(b + 2 * TILEB + cr1 * ROWB + cc1 * 16, Bhe + (size_t)(bn + cr1) * K + k0 + cc1 * 8);
        cp16(b + 3 * TILEB + cr0 * ROWB + cc0 * 16, Ble + (size_t)(bn + cr0) * K + k0 + cc0 * 8);
        cp16(b + 3 * TILEB + cr1 * ROWB + cc1 * 16, Ble + (size_t)(bn + cr1) * K + k0 + cc1 * 8);
        asm volatile("cp.async.commit_group;" ::: "memory");
    };

    load_chunk(0, 0);

    for (int c = 0; c < NC; c++) {
        const int cur = c & 1;
        if (c + 1 < NC) {
            load_chunk(c + 1, cur ^ 1);
            asm volatile("cp.async.wait_group 1;" ::: "memory");
        } else {
            asm volatile("cp.async.wait_group 0;" ::: "memory");
        }
        __syncthreads();

        const uint32_t As  = sb + (uint32_t)cur * BUFB;
        const uint32_t Als = As + TILEB;
        const uint32_t Bs  = As + 2 * TILEB;
        const uint32_t Bls = As + 3 * TILEB;

        #pragma unroll
        for (int ks = 0; ks < 2; ks++) {
            uint32_t ah[2][4], al[2][4], bb[4][4];
            // A fragments: M0=m0-7/klo M1=m8-15/klo M2=m0-7/khi M3=m8-15/khi
            #pragma unroll
            for (int ti = 0; ti < 2; ti++) {
                uint32_t off = (uint32_t)(wm + ti * 16 + (g & 1) * 8 + r8) * ROWB
                             + ks * 32 + (g >> 1) * 16;
                ldm4(ah[ti], As + off);
                ldm4(al[ti], Als + off);
            }
            // B hi fragments: pair p covers n-octets 2p,2p+1
            #pragma unroll
            for (int p = 0; p < 4; p++) {
                uint32_t off = (uint32_t)(wn + p * 16 + (g >> 1) * 8 + r8) * ROWB
                             + ks * 32 + (g & 1) * 16;
                ldm4(bb[p], Bs + off);
            }
            #pragma unroll
            for (int ti = 0; ti < 2; ti++)
                #pragma unroll
                for (int tj = 0; tj < 8; tj++) {
                    uint32_t b0 = bb[tj >> 1][(tj & 1) * 2];
                    uint32_t b1 = bb[tj >> 1][(tj & 1) * 2 + 1];
                    mma16816(acc[ti][tj], ah[ti], b0, b1);   // hi*hi
                    mma16816(acc[ti][tj], al[ti], b0, b1);   // lo*hi
                }
            // B lo fragments (reuse regs)
            #pragma unroll
            for (int p = 0; p < 4; p++) {
                uint32_t off = (uint32_t)(wn + p * 16 + (g >> 1) * 8 + r8) * ROWB
                             + ks * 32 + (g & 1) * 16;
                ldm4(bb[p], Bls + off);
            }
            #pragma unroll
            for (int ti = 0; ti < 2; ti++)
                #pragma unroll
                for (int tj = 0; tj < 8; tj++)
                    mma16816(acc[ti][tj], ah[ti],
                             bb[tj >> 1][(tj & 1) * 2], bb[tj >> 1][(tj & 1) * 2 + 1]); // hi*lo
        }
        __syncthreads();
    }

    // epilogue
    #pragma unroll
    for (int ti = 0; ti < 2; ti++)
        #pragma unroll
        for (int tj = 0; tj < 8; tj++) {
            const int row = bm + wm + ti * 16 + (lane >> 2);
            const int col = bn + wn + tj * 8 + (lane & 3) * 2;
            if (SPLIT_OUT) {
                __nv_bfloat16 h0, l0, h1, l1;
                split1(acc[ti][tj][0], h0, l0); split1(acc[ti][tj][1], h1, l1);
                __nv_bfloat16 hp[2] = {h0, h1}, lp[2] = {l0, l1};
                *(uint32_t*)(Ch + e * MN + (size_t)row * N + col) = *(uint32_t*)hp;
                *(uint32_t*)(Cl + e * MN + (size_t)row * N + col) = *(uint32_t*)lp;
                split1(acc[ti][tj][2], h0, l0); split1(acc[ti][tj][3], h1, l1);
                __nv_bfloat16 hq[2] = {h0, h1}, lq[2] = {l0, l1};
                *(uint32_t*)(Ch + e * MN + (size_t)(row + 8) * N + col) = *(uint32_t*)hq;
                *(uint32_t*)(Cl + e * MN + (size_t)(row + 8) * N + col) = *(uint32_t*)lq;
            } else {
                float* cp0 = Cf + e * MN + (size_t)row * N + col;
                float* cp1 = Cf + e * MN + (size_t)(row + 8) * N + col;
                *(float2*)cp0 = make_float2(acc[ti][tj][0], acc[ti][tj][1]);
                *(float2*)cp1 = make_float2(acc[ti][tj][2], acc[ti][tj][3]);
            }
        }
}

// ---------------- launcher ----------------
extern "C" void kernel_launch(void* const* d_in, const int* in_sizes, int n_in,
                              void* d_out, int out_size)
{
    (void)in_sizes; (void)n_in; (void)out_size;
    const float* x  = (const float*)d_in[0];
    const float* w1 = (const float*)d_in[1];
    const float* w2 = (const float*)d_in[2];
    const float* w3 = (const float*)d_in[3];
    const float* w4 = (const float*)d_in[4];
    float* out = (float*)d_out;

    __nv_bfloat16 *xh,*xl,*w1h,*w1l,*w2h,*w2l,*w3h,*w3l,*w4h,*w4l;
    __nv_bfloat16 *W12h,*W12l,*W34h,*W34l,*Wth,*Wtl;
    cudaGetSymbolAddress((void**)&xh,  g_xh);  cudaGetSymbolAddress((void**)&xl,  g_xl);
    cudaGetSymbolAddress((void**)&w1h, g_w1h); cudaGetSymbolAddress((void**)&w1l, g_w1l);
    cudaGetSymbolAddress((void**)&w2h, g_w2h); cudaGetSymbolAddress((void**)&w2l, g_w2l);
    cudaGetSymbolAddress((void**)&w3h, g_w3h); cudaGetSymbolAddress((void**)&w3l, g_w3l);
    cudaGetSymbolAddress((void**)&w4h, g_w4h); cudaGetSymbolAddress((void**)&w4l, g_w4l);
    cudaGetSymbolAddress((void**)&W12h, g_W12h); cudaGetSymbolAddress((void**)&W12l, g_W12l);
    cudaGetSymbolAddress((void**)&W34h, g_W34h); cudaGetSymbolAddress((void**)&W34l, g_W34l);
    cudaGetSymbolAddress((void**)&Wth,  g_Wth);  cudaGetSymbolAddress((void**)&Wtl,  g_Wtl);

    cudaFuncSetAttribute(gemm_hmma_x3<true>,  cudaFuncAttributeMaxDynamicSharedMemorySize, SMEMB);
    cudaFuncSetAttribute(gemm_hmma_x3<false>, cudaFuncAttributeMaxDynamicSharedMemorySize, SMEMB);

    // conversions
    {
        int n4 = NE * NT * NH / 4;
        split_rm<<<n4 / 256, 256>>>((const float4*)x, (uint2*)xh, (uint2*)xl, n4);
    }
    {
        int n4 = NE * NH * NI / 4;
        split_rm<<<n4 / 256, 256>>>((const float4*)w1, (uint2*)w1h, (uint2*)w1l, n4);
        split_rm<<<n4 / 256, 256>>>((const float4*)w3, (uint2*)w3h, (uint2*)w3l, n4);
    }
    split_tr<<<dim3(NH / 32, NI / 32, NE), 256>>>(w2, w2h, w2l, NI, NH);
    split_tr<<<dim3(NH / 32, NI / 32, NE), 256>>>(w4, w4h, w4l, NI, NH);

    // S1: W12 = w1 @ w2      (A=w1,  Bt=w2^T)  M=N=1024, K=512
    gemm_hmma_x3<true><<<dim3(NH / BN, NH / BM, NE), 256, SMEMB>>>(
        w1h, w1l, w2h, w2l, nullptr, W12h, W12l, NH, NH, NI);
    // S2: W34^T = w4^T @ w3^T (A=w4^T, Bt=w3)  M=N=1024, K=512
    gemm_hmma_x3<true><<<dim3(NH / BN, NH / BM, NE), 256, SMEMB>>>(
        w4h, w4l, w3h, w3l, nullptr, W34h, W34l, NH, NH, NI);
    // S3: W^T = W34^T @ W12^T (A=W34t, Bt=W12) M=N=K=1024
    gemm_hmma_x3<true><<<dim3(NH / BN, NH / BM, NE), 256, SMEMB>>>(
        W34h, W34l, W12h, W12l, nullptr, Wth, Wtl, NH, NH, NH);
    // S4: out = x @ W         (A=x,   Bt=W^T)  M=4096, N=K=1024
    gemm_hmma_x3<false><<<dim3(NH / BN, NT / BM, NE), 256, SMEMB>>>(
        xh, xl, Wth, Wtl, out, nullptr, nullptr, NT, NH, NH);
}